// round 15
// baseline (speedup 1.0000x reference)
#include <cuda_runtime.h>
#include <cuda_fp16.h>
#include <cstdint>

// ---------------- problem constants ----------------
#define B_TOK 8192
#define DIN   1024
#define HID   2048
#define DOUT  1024
#define NE    8
#define GHID  1024
#define CAP   8192

#define FLAG_RELU  1
#define FLAG_SPLIT 4
#define FLAG_DEST  8

// ---------------- tile geometry (packed 64B rows + XOR swizzle) ----------------
#define BM 128
#define BN 128
#define BK 32
#define BLK_B  8192               // block bytes: 128 rows x 64B (packed)
#define BLK_EL 4096

// element offset of (row r, col c) inside a 128x32 block, swizzled:
// physical 16B-chunk = (c>>3) ^ ((r>>1)&3)
__device__ __forceinline__ uint32_t sw_off(int r, int c) {
    return (uint32_t)(r * 32 + ((((c >> 3) ^ ((r >> 1) & 3)) << 3) | (c & 7)));
}

#define XT_TERM  ((size_t)(B_TOK/128) * (DIN/32) * BLK_EL)
#define GWT_TERM ((size_t)(GHID/128)  * (DIN/32) * BLK_EL)

// ---------------- scratch (static device globals; 128B aligned for bulk) ----------------
__device__ __align__(128) unsigned short g_xt [2*XT_TERM];                      // x tiled [hi|lo] (G1)
__device__ __align__(128) unsigned short g_gwt[2*GWT_TERM];                     // gw1^T tiled [hi|lo]
__device__ __align__(128) unsigned short g_xg [(size_t)NE*(CAP/128)*(DIN/32)*BLK_EL];  // gathered x tiled
__device__ __align__(128) unsigned short g_w1t[(size_t)NE*(HID/128)*(DIN/32)*BLK_EL];
__device__ __align__(128) unsigned short g_wpt[(size_t)NE*(HID/128)*(DIN/32)*BLK_EL];
__device__ __align__(128) unsigned short g_w2t[(size_t)NE*(HID/128)*(HID/32)*BLK_EL];
__device__ __align__(128) unsigned short g_w3t[(size_t)NE*(DOUT/128)*(HID/32)*BLK_EL];
__device__ __align__(128) unsigned short g_hst[(size_t)NE*(CAP/128)*(HID/32)*BLK_EL]; // h tiled
__device__ __align__(128) unsigned short g_ost[(size_t)NE*(CAP/128)*(HID/32)*BLK_EL]; // o tiled
__device__ float g_lpart [(size_t)(GHID/128)*B_TOK*NE];     // partial logits per G1 n-tile
__device__ float g_b23   [(size_t)NE*HID];                  // b2 + bp fused bias
__device__ int   g_counts[NE];
__device__ int   g_tokens[(size_t)NE*CAP];
__device__ float g_wts   [(size_t)NE*CAP];
__device__ int   g_dests [(size_t)NE*CAP];                  // token index per (expert,row)

// ---------------- PTX helpers (sm_90 baseline features only) ----------------
__device__ __forceinline__ uint32_t smem_u32(const void* p) {
    uint32_t a;
    asm("{ .reg .u64 t; cvta.to.shared.u64 t, %1; cvt.u32.u64 %0, t; }" : "=r"(a) : "l"(p));
    return a;
}
#define BULK_G2S(dst, src, nbytes, mbar) \
    asm volatile("cp.async.bulk.shared::cluster.global.mbarrier::complete_tx::bytes [%0], [%1], %2, [%3];" \
        :: "r"(dst), "l"(src), "r"(nbytes), "r"(mbar) : "memory")
#define MBAR_INIT(addr, cnt) \
    asm volatile("mbarrier.init.shared.b64 [%0], %1;" :: "r"(addr), "r"(cnt) : "memory")
#define MBAR_EXPECT_TX(addr, tx) \
    asm volatile("mbarrier.arrive.expect_tx.shared.b64 _, [%0], %1;" :: "r"(addr), "r"(tx) : "memory")
__device__ __forceinline__ void mbar_wait(uint32_t addr, uint32_t parity) {
    asm volatile("{\n\t.reg .pred P;\n"
        "LW%=:\n\tmbarrier.try_wait.parity.acquire.cta.shared::cta.b64 P, [%0], %1, 0x989680;\n"
        "\t@!P bra LW%=;\n\t}" :: "r"(addr), "r"(parity) : "memory");
}
#define LDSM4(r, addr) \
    asm volatile("ldmatrix.sync.aligned.m8n8.x4.shared.b16 {%0,%1,%2,%3}, [%4];" \
        : "=r"((r)[0]), "=r"((r)[1]), "=r"((r)[2]), "=r"((r)[3]) : "r"(addr))
#define MMA16816(d, a, b0, b1) \
    asm volatile("mma.sync.aligned.m16n8k16.row.col.f32.f16.f16.f32 " \
        "{%0,%1,%2,%3},{%4,%5,%6,%7},{%8,%9},{%0,%1,%2,%3};" \
        : "+f"((d)[0]), "+f"((d)[1]), "+f"((d)[2]), "+f"((d)[3]) \
        : "r"((a)[0]), "r"((a)[1]), "r"((a)[2]), "r"((a)[3]), "r"(b0), "r"(b1))
#define REDG_ADD_V2(addr, v0, v1) \
    asm volatile("red.global.add.v2.f32 [%0], {%1, %2};" :: "l"(addr), "f"(v0), "f"(v1) : "memory")

// ---------------- HMMA GEMM: tile 128x128x32, bulk tiled operands ----------------
// KPS k-blocks per pipeline stage. Segmented K via kcSplit.
// LG=1: gating epilogue — compute partial logits relu(v)·gw2 instead of storing.
template<int ATERMS, int BTERMS, int NSTAGES, int KPS, int LG>
__global__ __launch_bounds__(256, 2) void mma_gemm(
    const unsigned short* __restrict__ Atiled, size_t aTermOff,
    const unsigned short* __restrict__ At2, int aMtPerE,
    const unsigned short* __restrict__ Btiled, size_t bTermOff,
    const unsigned short* __restrict__ Bt2,
    const float* __restrict__ bias, int bStrideE,
    float* __restrict__ outF, unsigned short* __restrict__ outS,
    const float* __restrict__ scales, const int* __restrict__ dests,
    const int* __restrict__ counts, int Mfixed,
    int KPC, int kcSplit, int N, int flags)
{
    constexpr uint32_t STAGE_B = (ATERMS + BTERMS) * KPS * BLK_B;

    const int e  = blockIdx.z;
    const int M  = counts ? counts[e] : Mfixed;
    const int m0 = blockIdx.y * BM;
    if (m0 >= M) return;
    const int n0 = blockIdx.x * BN;

    const int NT   = N >> 7;
    const int kpc2 = KPC - kcSplit;

    extern __shared__ char smem[];
    const uint32_t sbase = smem_u32(smem);
    const uint32_t mbar0 = sbase + NSTAGES * STAGE_B;

    const int tid  = threadIdx.x;
    const int wid  = tid >> 5;
    const int lane = tid & 31;

    const size_t aTile = (size_t)(e * aMtPerE + blockIdx.y);
    const size_t bTile = (size_t)(e * NT + blockIdx.x);

    if (tid == 0) {
        #pragma unroll
        for (int s = 0; s < NSTAGES; s++) MBAR_INIT(mbar0 + s * 8, 1);
    }
    __syncthreads();

    // ---- fragment smem addresses (kb=0, term0): warp tile 64x32, swizzled chunks ----
    const int wm = wid & 1;
    const int wn = wid >> 1;
    uint32_t aAddr[4][2], bAddr[2][2];
    {
        int arow0 = wm * 64 + (lane & 15);
        int alc0  = (lane >> 4);
        int brow0 = wn * 32 + ((lane >> 4) * 8) + (lane & 7);
        int blc0  = ((lane >> 3) & 1);
        #pragma unroll
        for (int ks = 0; ks < 2; ks++) {
            #pragma unroll
            for (int mt = 0; mt < 4; mt++) {
                int r  = arow0 + mt * 16;
                int pc = (ks * 2 + alc0) ^ ((r >> 1) & 3);
                aAddr[mt][ks] = sbase + (uint32_t)(r * 64 + pc * 16);
            }
            #pragma unroll
            for (int nt2 = 0; nt2 < 2; nt2++) {
                int r  = brow0 + nt2 * 16;
                int pc = (ks * 2 + blc0) ^ ((r >> 1) & 3);
                bAddr[nt2][ks] = sbase + ATERMS * KPS * BLK_B + (uint32_t)(r * 64 + pc * 16);
            }
        }
    }

    float acc[4][4][4];
    #pragma unroll
    for (int mt = 0; mt < 4; mt++)
        #pragma unroll
        for (int nt = 0; nt < 4; nt++)
            #pragma unroll
            for (int k = 0; k < 4; k++) acc[mt][nt][k] = 0.0f;

    const int NITS = KPC / KPS;

    auto load_stage = [&](int s, int sit) {
        if (tid == 0) {
            const uint32_t stg = sbase + s * STAGE_B;
            const uint32_t mb = mbar0 + s * 8;
            MBAR_EXPECT_TX(mb, STAGE_B);
            #pragma unroll
            for (int kb = 0; kb < KPS; kb++) {
                int gk = sit * KPS + kb;
                const unsigned short* aSrc;
                const unsigned short* bSrc;
                if (gk < kcSplit) {
                    aSrc = Atiled + (aTile * kcSplit + gk) * BLK_EL;
                    bSrc = Btiled + (bTile * kcSplit + gk) * BLK_EL;
                } else {
                    aSrc = At2 + (aTile * kpc2 + (gk - kcSplit)) * BLK_EL;
                    bSrc = Bt2 + (bTile * kpc2 + (gk - kcSplit)) * BLK_EL;
                }
                BULK_G2S(stg + kb * BLK_B, aSrc, BLK_B, mb);
                if (ATERMS == 2)
                    BULK_G2S(stg + (KPS + kb) * BLK_B,
                             Atiled + aTermOff + (aTile * kcSplit + gk) * BLK_EL, BLK_B, mb);
                BULK_G2S(stg + (ATERMS * KPS + kb) * BLK_B, bSrc, BLK_B, mb);
                if (BTERMS == 2)
                    BULK_G2S(stg + ((ATERMS + 1) * KPS + kb) * BLK_B,
                             Btiled + bTermOff + (bTile * kcSplit + gk) * BLK_EL, BLK_B, mb);
            }
        }
    };

    #pragma unroll
    for (int s = 0; s < NSTAGES - 1; s++)
        if (s < NITS) load_stage(s, s);

    for (int sit = 0; sit < NITS; sit++) {
        mbar_wait(mbar0 + (sit % NSTAGES) * 8, (sit / NSTAGES) & 1);
        __syncthreads();
        if (sit + NSTAGES - 1 < NITS) load_stage((sit + NSTAGES - 1) % NSTAGES, sit + NSTAGES - 1);

        const uint32_t soff = (sit % NSTAGES) * STAGE_B;
        #pragma unroll
        for (int kb = 0; kb < KPS; kb++) {
            const uint32_t ko = soff + kb * BLK_B;
            #pragma unroll
            for (int ks = 0; ks < 2; ks++) {
                uint32_t af0[4][4], bf[2][4];
                #pragma unroll
                for (int mt = 0; mt < 4; mt++) LDSM4(af0[mt], aAddr[mt][ks] + ko);
                #pragma unroll
                for (int nt2 = 0; nt2 < 2; nt2++) LDSM4(bf[nt2], bAddr[nt2][ks] + ko);
                #pragma unroll
                for (int mt = 0; mt < 4; mt++)
                    #pragma unroll
                    for (int nt = 0; nt < 4; nt++)
                        MMA16816(acc[mt][nt], af0[mt], bf[nt >> 1][(nt & 1) * 2], bf[nt >> 1][(nt & 1) * 2 + 1]);
                if (ATERMS == 2) {
                    uint32_t af1[4][4];
                    #pragma unroll
                    for (int mt = 0; mt < 4; mt++) LDSM4(af1[mt], aAddr[mt][ks] + ko + KPS * BLK_B);
                    #pragma unroll
                    for (int mt = 0; mt < 4; mt++)
                        #pragma unroll
                        for (int nt = 0; nt < 4; nt++)
                            MMA16816(acc[mt][nt], af1[mt], bf[nt >> 1][(nt & 1) * 2], bf[nt >> 1][(nt & 1) * 2 + 1]);
                }
                if (BTERMS == 2) {
                    uint32_t bfl[2][4];
                    #pragma unroll
                    for (int nt2 = 0; nt2 < 2; nt2++) LDSM4(bfl[nt2], bAddr[nt2][ks] + ko + KPS * BLK_B);
                    #pragma unroll
                    for (int mt = 0; mt < 4; mt++)
                        #pragma unroll
                        for (int nt = 0; nt < 4; nt++)
                            MMA16816(acc[mt][nt], af0[mt], bfl[nt >> 1][(nt & 1) * 2], bfl[nt >> 1][(nt & 1) * 2 + 1]);
                }
            }
        }
    }

    // ---- epilogue ----
    const float* biasE = bias + (size_t)e * bStrideE;
    const int cq = (lane & 3) * 2;
    const int r0 = lane >> 2;
    float b2v[4][2];
    #pragma unroll
    for (int nt = 0; nt < 4; nt++) {
        int n = n0 + wn * 32 + nt * 8 + cq;
        b2v[nt][0] = biasE[n];
        b2v[nt][1] = biasE[n + 1];
    }

    if (LG) {
        // gating epilogue: partial logits = relu(v) . gw2  (scales == gw2 [GHID][NE])
        float* sp = (float*)(smem + NSTAGES * STAGE_B + 64);   // [4 wn][128 rows][NE]
        const float* gw2p = scales;
        #pragma unroll
        for (int mt = 0; mt < 4; mt++) {
            #pragma unroll
            for (int h = 0; h < 2; h++) {
                int row = wm * 64 + mt * 16 + r0 + h * 8;   // local row 0..127
                float p[NE];
                #pragma unroll
                for (int e2 = 0; e2 < NE; e2++) p[e2] = 0.0f;
                #pragma unroll
                for (int nt = 0; nt < 4; nt++) {
                    int n = n0 + wn * 32 + nt * 8 + cq;
                    float v0 = acc[mt][nt][h * 2]     + b2v[nt][0];
                    float v1 = acc[mt][nt][h * 2 + 1] + b2v[nt][1];
                    v0 = fmaxf(v0, 0.0f); v1 = fmaxf(v1, 0.0f);
                    const float* ga = gw2p + (size_t)n * NE;
                    #pragma unroll
                    for (int e2 = 0; e2 < NE; e2++)
                        p[e2] += v0 * ga[e2] + v1 * ga[NE + e2];
                }
                #pragma unroll
                for (int e2 = 0; e2 < NE; e2++) {
                    p[e2] += __shfl_xor_sync(0xFFFFFFFFu, p[e2], 1);
                    p[e2] += __shfl_xor_sync(0xFFFFFFFFu, p[e2], 2);
                }
                if ((lane & 3) == 0) {
                    #pragma unroll
                    for (int e2 = 0; e2 < NE; e2++)
                        sp[((wn * 128) + row) * NE + e2] = p[e2];
                }
            }
        }
        __syncthreads();
        for (int idx = tid; idx < 128 * NE; idx += 256) {
            int row = idx >> 3, e2 = idx & 7;
            float s = sp[row * NE + e2] + sp[(128 + row) * NE + e2]
                    + sp[(256 + row) * NE + e2] + sp[(384 + row) * NE + e2];
            outF[(size_t)blockIdx.x * B_TOK * NE + (size_t)(m0 + row) * NE + e2] = s;
        }
        return;
    }

    #pragma unroll
    for (int mt = 0; mt < 4; mt++) {
        #pragma unroll
        for (int h = 0; h < 2; h++) {
            int row = m0 + wm * 64 + mt * 16 + r0 + h * 8;
            if (row >= M) continue;
            size_t erow = (size_t)e * CAP + row;
            float sc = 1.0f;
            int   tok = 0;
            if (flags & FLAG_DEST) {
                sc  = scales[erow];
                tok = dests[erow];
            }
            #pragma unroll
            for (int nt = 0; nt < 4; nt++) {
                int n = n0 + wn * 32 + nt * 8 + cq;
                float v0 = acc[mt][nt][h * 2]     + b2v[nt][0];
                float v1 = acc[mt][nt][h * 2 + 1] + b2v[nt][1];
                if (flags & FLAG_RELU) { v0 = fmaxf(v0, 0.0f); v1 = fmaxf(v1, 0.0f); }
                if (flags & FLAG_SPLIT) {
                    size_t blk = ((erow >> 7) * (size_t)(N >> 5) + (size_t)(n >> 5)) * BLK_EL;
                    *(__half2*)((__half*)outS + blk + sw_off((int)(erow & 127), n & 31)) =
                        __halves2half2(__float2half_rn(v0), __float2half_rn(v1));
                } else if (flags & FLAG_DEST) {
                    // vector reduction: one red.v2 per (v0,v1) pair; 2 commutative adds/elem -> deterministic
                    REDG_ADD_V2(outF + (size_t)tok * N + n, v0 * sc, v1 * sc);
                } else {
                    float2 o2; o2.x = v0; o2.y = v1;
                    *(float2*)(outF + (size_t)row * N + n) = o2;
                }
            }
        }
    }
}

// ---------------- fused prep: all weight conversions in ONE kernel ----------------
#define TW1  ((HID/32)*(DIN/32)*NE)     // 16384
#define TWP  TW1
#define TW2  ((HID/32)*(HID/32)*NE)     // 32768
#define TW3  ((DOUT/32)*(HID/32)*NE)    // 16384
#define TGW  ((GHID/32)*(DIN/32))       // 1024
#define TWTOT (TW1+TWP+TW2+TW3+TGW)

__device__ __forceinline__ void conv_tile(const float* W, unsigned short* Wt,
                                          int K, int N, size_t termOff,
                                          int e, int n0, int k0,
                                          float t[32][33])
{
    const float* We = W + (size_t)e * K * N;
    #pragma unroll
    for (int j = 0; j < 4; j++) {
        int k = k0 + threadIdx.y + j * 8;
        t[threadIdx.y + j * 8][threadIdx.x] = We[(size_t)k * N + n0 + threadIdx.x];
    }
    __syncthreads();
    const size_t blkBase = (((size_t)e * (N >> 7) + (size_t)(n0 >> 7)) * (K >> 5) + (size_t)(k0 >> 5)) * BLK_EL;
    #pragma unroll
    for (int j = 0; j < 4; j++) {
        int n = n0 + threadIdx.y + j * 8;
        int k = k0 + threadIdx.x;
        float v = t[threadIdx.x][threadIdx.y + j * 8];
        __half hi = __float2half_rn(v);
        size_t off = blkBase + sw_off(n & 127, k & 31);
        ((__half*)Wt)[off] = hi;
        if (termOff) ((__half*)Wt)[termOff + off] = __float2half_rn(v - __half2float(hi));
    }
}

__global__ void prep_w(const float* __restrict__ w1, const float* __restrict__ wp,
                       const float* __restrict__ w2, const float* __restrict__ w3,
                       const float* __restrict__ gw1,
                       unsigned short* __restrict__ w1t, unsigned short* __restrict__ wpt,
                       unsigned short* __restrict__ w2t, unsigned short* __restrict__ w3t,
                       unsigned short* __restrict__ gwt)
{
    __shared__ float t[32][33];
    int b = blockIdx.x;
    if (b < TW1) {
        int e = b / ((HID/32)*(DIN/32)); int r = b % ((HID/32)*(DIN/32));
        conv_tile(w1, w1t, DIN, HID, 0, e, (r % (HID/32)) * 32, (r / (HID/32)) * 32, t);
    } else if ((b -= TW1) < TWP) {
        int e = b / ((HID/32)*(DIN/32)); int r = b % ((HID/32)*(DIN/32));
        conv_tile(wp, wpt, DIN, HID, 0, e, (r % (HID/32)) * 32, (r / (HID/32)) * 32, t);
    } else if ((b -= TWP) < TW2) {
        int e = b / ((HID/32)*(HID/32)); int r = b % ((HID/32)*(HID/32));
        conv_tile(w2, w2t, HID, HID, 0, e, (r % (HID/32)) * 32, (r / (HID/32)) * 32, t);
    } else if ((b -= TW2) < TW3) {
        int e = b / ((DOUT/32)*(HID/32)); int r = b % ((DOUT/32)*(HID/32));
        conv_tile(w3, w3t, HID, DOUT, 0, e, (r % (DOUT/32)) * 32, (r / (DOUT/32)) * 32, t);
    } else {
        b -= TW3;
        conv_tile(gw1, gwt, DIN, GHID, GWT_TERM, 0, (b % (GHID/32)) * 32, (b / (GHID/32)) * 32, t);
    }
}

// ---------------- fused prep: zero_out + convert_x + bias_fuse + counts ----------------
#define ZN4   ((size_t)B_TOK * DOUT / 4)
#define XTOT  ((size_t)B_TOK * DIN)
__global__ __launch_bounds__(256) void prep_small(float4* __restrict__ out,
                                                  const float* __restrict__ x,
                                                  unsigned short* __restrict__ xt,
                                                  const float* __restrict__ b2,
                                                  const float* __restrict__ bp,
                                                  float* __restrict__ b23)
{
    size_t idx = (size_t)blockIdx.x * blockDim.x + threadIdx.x;
    if (idx < ZN4) {
        out[idx] = make_float4(0.f, 0.f, 0.f, 0.f);
    }
    if (idx < XTOT) {
        size_t t = idx / DIN;
        int    k = (int)(idx % DIN);
        float v = x[idx];
        __half hi = __float2half_rn(v);
        __half lo = __float2half_rn(v - __half2float(hi));
        size_t blk = ((t >> 7) * (size_t)(DIN >> 5) + (size_t)(k >> 5)) * BLK_EL
                   + sw_off((int)(t & 127), k & 31);
        ((__half*)xt)[blk]           = hi;
        ((__half*)xt)[XT_TERM + blk] = lo;
    }
    if (idx < NE * HID) b23[idx] = b2[idx] + bp[idx];
    if (idx < NE) g_counts[idx] = 0;
}

// ---------------- gather routed x: vectorized, one 16B chunk per thread ----------------
__global__ __launch_bounds__(256) void tile_gather_x(const float* __restrict__ x,
                                                     unsigned short* __restrict__ xg)
{
    const int e  = blockIdx.y;
    const int mt = blockIdx.x;
    const int M  = g_counts[e];
    const int m0 = mt * 128;
    if (m0 >= M) return;
    const int nrows = min(128, M - m0);
    const size_t base = ((size_t)(e * (CAP / 128) + mt) * (DIN / 32)) * BLK_EL;
    const int nchunks = nrows * (DIN / 8);
    for (int idx = threadIdx.x; idx < nchunks; idx += 256) {
        int row = idx >> 7;
        int c8  = idx & 127;
        int k   = c8 * 8;
        int tok = g_tokens[e * CAP + m0 + row];
        const float4* xp = (const float4*)(x + (size_t)tok * DIN + k);
        float4 a = xp[0], b = xp[1];
        __half h[8];
        h[0] = __float2half_rn(a.x); h[1] = __float2half_rn(a.y);
        h[2] = __float2half_rn(a.z); h[3] = __float2half_rn(a.w);
        h[4] = __float2half_rn(b.x); h[5] = __float2half_rn(b.y);
        h[6] = __float2half_rn(b.z); h[7] = __float2half_rn(b.w);
        size_t off = base + (size_t)(k >> 5) * BLK_EL + sw_off(row, k & 31);
        *(uint4*)((__half*)xg + off) = *(uint4*)h;
    }
}

// ---------------- routing: fused partial-reduce + top-2 + softmax + scatter ----------------
__global__ __launch_bounds__(256) void route_kernel(const float* __restrict__ lpart,
                                                    const float* __restrict__ gb2)
{
    int t = blockIdx.x * blockDim.x + threadIdx.x;
    if (t >= B_TOK) return;
    float v[NE];
    #pragma unroll
    for (int e = 0; e < NE; e++) v[e] = gb2[e];
    #pragma unroll
    for (int bx = 0; bx < GHID / 128; bx++) {
        const float* lp = lpart + (size_t)bx * B_TOK * NE + (size_t)t * NE;
        #pragma unroll
        for (int e = 0; e < NE; e++) v[e] += lp[e];
    }
    int i0 = 0;
    #pragma unroll
    for (int e = 1; e < NE; e++) if (v[e] > v[i0]) i0 = e;
    int i1 = (i0 == 0) ? 1 : 0;
    #pragma unroll
    for (int e = 0; e < NE; e++) if (e != i0 && v[e] > v[i1]) i1 = e;
    float b = __expf(v[i1] - v[i0]);
    float s = 1.0f + b;
    float w0 = 1.0f / s;
    float w1 = b / s;

    int p0 = atomicAdd(&g_counts[i0], 1);
    g_tokens[i0 * CAP + p0] = t;
    g_wts[i0 * CAP + p0]    = w0;
    g_dests[i0 * CAP + p0]  = t;

    int p1 = atomicAdd(&g_counts[i1], 1);
    g_tokens[i1 * CAP + p1] = t;
    g_wts[i1 * CAP + p1]    = w1;
    g_dests[i1 * CAP + p1]  = t;
}

// ---------------- host ----------------
#define NST_E 3
#define KPS_E 2
#define DSM_E (NST_E * 2 * KPS_E * BLK_B + 64)              // 98368; 2 CTAs/SM
#define DSM_G (2 * 4 * BLK_B + 64 + 4 * 128 * NE * 4)       // 81984; 2 CTAs/SM

extern "C" void kernel_launch(void* const* d_in, const int* in_sizes, int n_in,
                              void* d_out, int out_size) {
    const float* x   = (const float*)d_in[0];
    const float* w1  = (const float*)d_in[1];
    const float* b1  = (const float*)d_in[2];
    const float* w2  = (const float*)d_in[3];
    const float* b2  = (const float*)d_in[4];
    const float* w3  = (const float*)d_in[5];
    const float* b3  = (const float*)d_in[6];
    const float* wp  = (const float*)d_in[7];
    const float* bp  = (const float*)d_in[8];
    const float* gw1 = (const float*)d_in[9];
    const float* gb1 = (const float*)d_in[10];
    const float* gw2 = (const float*)d_in[11];
    const float* gb2 = (const float*)d_in[12];
    float* out = (float*)d_out;

    unsigned short *p_xt, *p_gwt, *p_xg, *p_w1t, *p_wpt, *p_w2t, *p_w3t, *p_hst, *p_ost;
    float *p_lpart, *p_b23, *p_wts;
    int *p_counts, *p_tokens, *p_dests;
    cudaGetSymbolAddress((void**)&p_xt,     g_xt);
    cudaGetSymbolAddress((void**)&p_gwt,    g_gwt);
    cudaGetSymbolAddress((void**)&p_xg,     g_xg);
    cudaGetSymbolAddress((void**)&p_w1t,    g_w1t);
    cudaGetSymbolAddress((void**)&p_wpt,    g_wpt);
    cudaGetSymbolAddress((void**)&p_w2t,    g_w2t);
    cudaGetSymbolAddress((void**)&p_w3t,    g_w3t);
    cudaGetSymbolAddress((void**)&p_hst,    g_hst);
    cudaGetSymbolAddress((void**)&p_ost,    g_ost);
    cudaGetSymbolAddress((void**)&p_lpart,  g_lpart);
    cudaGetSymbolAddress((void**)&p_b23,    g_b23);
    cudaGetSymbolAddress((void**)&p_wts,    g_wts);
    cudaGetSymbolAddress((void**)&p_counts, g_counts);
    cudaGetSymbolAddress((void**)&p_tokens, g_tokens);
    cudaGetSymbolAddress((void**)&p_dests,  g_dests);

    cudaFuncSetAttribute((const void*)mma_gemm<1,1,NST_E,KPS_E,0>,
                         cudaFuncAttributeMaxDynamicSharedMemorySize, DSM_E);
    cudaFuncSetAttribute((const void*)mma_gemm<2,2,2,1,1>,
                         cudaFuncAttributeMaxDynamicSharedMemorySize, DSM_G);

    // prep: zero out + x split/tile + bias fuse + zero counts (1 launch), weights (1 launch)
    {
        size_t n = XTOT;
        prep_small<<<(unsigned)((n + 255) / 256), 256>>>((float4*)out, x, p_xt, b2, bp, p_b23);
    }
    prep_w<<<TWTOT, dim3(32, 8)>>>(w1, wp, w2, w3, gw1, p_w1t, p_wpt, p_w2t, p_w3t, p_gwt);

    // G1: 3-term gating GEMM with fused partial-logit epilogue (relu(x@gw1+gb1)·gw2)
    mma_gemm<2,2,2,1,1><<<dim3(GHID / BN, B_TOK / BM, 1), 256, DSM_G>>>(
        p_xt, XT_TERM, nullptr, B_TOK / 128,
        p_gwt, GWT_TERM, nullptr,
        gb1, 0,
        p_lpart, nullptr, gw2, nullptr, nullptr, B_TOK,
        DIN / 32, DIN / 32, GHID, FLAG_RELU);

    // routing (fused logit reduce + top-2 + softmax + scatter)
    route_kernel<<<B_TOK / 256, 256>>>(p_lpart, gb2);

    // gather routed x into tiled layout (vectorized 16B chunks)
    tile_gather_x<<<dim3(CAP / 128, NE), 256>>>(x, p_xg);

    // L1: h = relu(x_g @ w1 + b1) -> tiled fp16
    mma_gemm<1,1,NST_E,KPS_E,0><<<dim3(HID / BN, CAP / BM, NE), 256, DSM_E>>>(
        p_xg, 0, nullptr, CAP / 128,
        p_w1t, 0, nullptr,
        b1, HID,
        nullptr, p_hst, nullptr, nullptr, p_counts, 0,
        DIN / 32, DIN / 32, HID, FLAG_RELU | FLAG_SPLIT);

    // L3 (L2 fused via K-concat): o = relu([h|x_g] @ [w2;wp] + b2+bp) -> tiled fp16
    mma_gemm<1,1,NST_E,KPS_E,0><<<dim3(HID / BN, CAP / BM, NE), 256, DSM_E>>>(
        p_hst, 0, p_xg, CAP / 128,
        p_w2t, 0, p_wpt,
        p_b23, HID,
        nullptr, p_ost, nullptr, nullptr, p_counts, 0,
        (HID + DIN) / 32, HID / 32, HID, FLAG_RELU | FLAG_SPLIT);

    // L4: out[tok] += (o @ w3 + b3) * gate_w   (vector red.global, 2 adds per element)
    mma_gemm<1,1,NST_E,KPS_E,0><<<dim3(DOUT / BN, CAP / BM, NE), 256, DSM_E>>>(
        p_ost, 0, nullptr, CAP / 128,
        p_w3t, 0, nullptr,
        b3, DOUT,
        out, nullptr, p_wts, p_dests, p_counts, 0,
        HID / 32, HID / 32, DOUT, FLAG_DEST);
}

// round 17
// speedup vs baseline: 1.0325x; 1.0325x over previous
#include <cuda_runtime.h>
#include <cuda_fp16.h>
#include <cstdint>

// ---------------- problem constants ----------------
#define B_TOK 8192
#define DIN   1024
#define HID   2048
#define DOUT  1024
#define NE    8
#define GHID  1024
#define CAP   8192

#define FLAG_RELU  1
#define FLAG_SPLIT 4
#define FLAG_DEST  8

// ---------------- tile geometry (packed 64B rows + XOR swizzle) ----------------
#define BM 128
#define BN 128
#define BK 32
#define BLK_B  8192               // block bytes: 128 rows x 64B (packed)
#define BLK_EL 4096

// element offset of (row r, col c) inside a 128x32 block, swizzled:
// physical 16B-chunk = (c>>3) ^ ((r>>1)&3)
__device__ __forceinline__ uint32_t sw_off(int r, int c) {
    return (uint32_t)(r * 32 + ((((c >> 3) ^ ((r >> 1) & 3)) << 3) | (c & 7)));
}

#define XT_TERM  ((size_t)(B_TOK/128) * (DIN/32) * BLK_EL)
#define GWT_TERM ((size_t)(GHID/128)  * (DIN/32) * BLK_EL)

// ---------------- scratch (static device globals; 128B aligned for bulk) ----------------
__device__ __align__(128) unsigned short g_xt [2*XT_TERM];                      // x tiled [hi|lo] (G1)
__device__ __align__(128) unsigned short g_gwt[2*GWT_TERM];                     // gw1^T tiled [hi|lo]
__device__ __align__(128) unsigned short g_xg [(size_t)NE*(CAP/128)*(DIN/32)*BLK_EL];  // gathered x tiled
__device__ __align__(128) unsigned short g_w1t[(size_t)NE*(HID/128)*(DIN/32)*BLK_EL];
__device__ __align__(128) unsigned short g_wpt[(size_t)NE*(HID/128)*(DIN/32)*BLK_EL];
__device__ __align__(128) unsigned short g_w2t[(size_t)NE*(HID/128)*(HID/32)*BLK_EL];
__device__ __align__(128) unsigned short g_w3t[(size_t)NE*(DOUT/128)*(HID/32)*BLK_EL];
__device__ __align__(128) unsigned short g_hst[(size_t)NE*(CAP/128)*(HID/32)*BLK_EL]; // h tiled
__device__ __align__(128) unsigned short g_ost[(size_t)NE*(CAP/128)*(HID/32)*BLK_EL]; // o tiled
__device__ float g_lpart [(size_t)(GHID/128)*B_TOK*NE];     // partial logits per G1 n-tile
__device__ float g_b23   [(size_t)NE*HID];                  // b2 + bp fused bias
__device__ int   g_counts[NE];
__device__ int   g_tokens[(size_t)NE*CAP];
__device__ float g_wts   [(size_t)NE*CAP];
__device__ int   g_dests [(size_t)NE*CAP];                  // token index per (expert,row)

// ---------------- PTX helpers (sm_90 baseline features only) ----------------
__device__ __forceinline__ uint32_t smem_u32(const void* p) {
    uint32_t a;
    asm("{ .reg .u64 t; cvta.to.shared.u64 t, %1; cvt.u32.u64 %0, t; }" : "=r"(a) : "l"(p));
    return a;
}
#define BULK_G2S(dst, src, nbytes, mbar) \
    asm volatile("cp.async.bulk.shared::cluster.global.mbarrier::complete_tx::bytes [%0], [%1], %2, [%3];" \
        :: "r"(dst), "l"(src), "r"(nbytes), "r"(mbar) : "memory")
#define MBAR_INIT(addr, cnt) \
    asm volatile("mbarrier.init.shared.b64 [%0], %1;" :: "r"(addr), "r"(cnt) : "memory")
#define MBAR_EXPECT_TX(addr, tx) \
    asm volatile("mbarrier.arrive.expect_tx.shared.b64 _, [%0], %1;" :: "r"(addr), "r"(tx) : "memory")
__device__ __forceinline__ void mbar_wait(uint32_t addr, uint32_t parity) {
    asm volatile("{\n\t.reg .pred P;\n"
        "LW%=:\n\tmbarrier.try_wait.parity.acquire.cta.shared::cta.b64 P, [%0], %1, 0x989680;\n"
        "\t@!P bra LW%=;\n\t}" :: "r"(addr), "r"(parity) : "memory");
}
#define LDSM4(r, addr) \
    asm volatile("ldmatrix.sync.aligned.m8n8.x4.shared.b16 {%0,%1,%2,%3}, [%4];" \
        : "=r"((r)[0]), "=r"((r)[1]), "=r"((r)[2]), "=r"((r)[3]) : "r"(addr))
#define MMA16816(d, a, b0, b1) \
    asm volatile("mma.sync.aligned.m16n8k16.row.col.f32.f16.f16.f32 " \
        "{%0,%1,%2,%3},{%4,%5,%6,%7},{%8,%9},{%0,%1,%2,%3};" \
        : "+f"((d)[0]), "+f"((d)[1]), "+f"((d)[2]), "+f"((d)[3]) \
        : "r"((a)[0]), "r"((a)[1]), "r"((a)[2]), "r"((a)[3]), "r"(b0), "r"(b1))
#define REDG_ADD_V2(addr, v0, v1) \
    asm volatile("red.global.add.v2.f32 [%0], {%1, %2};" :: "l"(addr), "f"(v0), "f"(v1) : "memory")

// ---------------- HMMA GEMM: tile 128x128x32, bulk tiled operands ----------------
// KPS k-blocks per pipeline stage. Segmented K via kcSplit.
// LG=1: gating epilogue — compute partial logits relu(v)·gw2 instead of storing.
template<int ATERMS, int BTERMS, int NSTAGES, int KPS, int LG>
__global__ __launch_bounds__(256, 2) void mma_gemm(
    const unsigned short* __restrict__ Atiled, size_t aTermOff,
    const unsigned short* __restrict__ At2, int aMtPerE,
    const unsigned short* __restrict__ Btiled, size_t bTermOff,
    const unsigned short* __restrict__ Bt2,
    const float* __restrict__ bias, int bStrideE,
    float* __restrict__ outF, unsigned short* __restrict__ outS,
    const float* __restrict__ scales, const int* __restrict__ dests,
    const int* __restrict__ counts, int Mfixed,
    int KPC, int kcSplit, int N, int flags)
{
    constexpr uint32_t STAGE_B = (ATERMS + BTERMS) * KPS * BLK_B;

    const int e  = blockIdx.z;
    const int M  = counts ? counts[e] : Mfixed;
    const int m0 = blockIdx.y * BM;
    if (m0 >= M) return;
    const int n0 = blockIdx.x * BN;

    const int NT   = N >> 7;
    const int kpc2 = KPC - kcSplit;

    extern __shared__ char smem[];
    const uint32_t sbase = smem_u32(smem);
    const uint32_t mbar0 = sbase + NSTAGES * STAGE_B;

    const int tid  = threadIdx.x;
    const int wid  = tid >> 5;
    const int lane = tid & 31;

    const size_t aTile = (size_t)(e * aMtPerE + blockIdx.y);
    const size_t bTile = (size_t)(e * NT + blockIdx.x);

    if (tid == 0) {
        #pragma unroll
        for (int s = 0; s < NSTAGES; s++) MBAR_INIT(mbar0 + s * 8, 1);
    }
    __syncthreads();

    // ---- fragment smem addresses (kb=0, term0): warp tile 64x32, swizzled chunks ----
    const int wm = wid & 1;
    const int wn = wid >> 1;
    uint32_t aAddr[4][2], bAddr[2][2];
    {
        int arow0 = wm * 64 + (lane & 15);
        int alc0  = (lane >> 4);
        int brow0 = wn * 32 + ((lane >> 4) * 8) + (lane & 7);
        int blc0  = ((lane >> 3) & 1);
        #pragma unroll
        for (int ks = 0; ks < 2; ks++) {
            #pragma unroll
            for (int mt = 0; mt < 4; mt++) {
                int r  = arow0 + mt * 16;
                int pc = (ks * 2 + alc0) ^ ((r >> 1) & 3);
                aAddr[mt][ks] = sbase + (uint32_t)(r * 64 + pc * 16);
            }
            #pragma unroll
            for (int nt2 = 0; nt2 < 2; nt2++) {
                int r  = brow0 + nt2 * 16;
                int pc = (ks * 2 + blc0) ^ ((r >> 1) & 3);
                bAddr[nt2][ks] = sbase + ATERMS * KPS * BLK_B + (uint32_t)(r * 64 + pc * 16);
            }
        }
    }

    float acc[4][4][4];
    #pragma unroll
    for (int mt = 0; mt < 4; mt++)
        #pragma unroll
        for (int nt = 0; nt < 4; nt++)
            #pragma unroll
            for (int k = 0; k < 4; k++) acc[mt][nt][k] = 0.0f;

    const int NITS = KPC / KPS;

    auto load_stage = [&](int s, int sit) {
        if (tid == 0) {
            const uint32_t stg = sbase + s * STAGE_B;
            const uint32_t mb = mbar0 + s * 8;
            MBAR_EXPECT_TX(mb, STAGE_B);
            #pragma unroll
            for (int kb = 0; kb < KPS; kb++) {
                int gk = sit * KPS + kb;
                const unsigned short* aSrc;
                const unsigned short* bSrc;
                if (gk < kcSplit) {
                    aSrc = Atiled + (aTile * kcSplit + gk) * BLK_EL;
                    bSrc = Btiled + (bTile * kcSplit + gk) * BLK_EL;
                } else {
                    aSrc = At2 + (aTile * kpc2 + (gk - kcSplit)) * BLK_EL;
                    bSrc = Bt2 + (bTile * kpc2 + (gk - kcSplit)) * BLK_EL;
                }
                BULK_G2S(stg + kb * BLK_B, aSrc, BLK_B, mb);
                if (ATERMS == 2)
                    BULK_G2S(stg + (KPS + kb) * BLK_B,
                             Atiled + aTermOff + (aTile * kcSplit + gk) * BLK_EL, BLK_B, mb);
                BULK_G2S(stg + (ATERMS * KPS + kb) * BLK_B, bSrc, BLK_B, mb);
                if (BTERMS == 2)
                    BULK_G2S(stg + ((ATERMS + 1) * KPS + kb) * BLK_B,
                             Btiled + bTermOff + (bTile * kcSplit + gk) * BLK_EL, BLK_B, mb);
            }
        }
    };

    #pragma unroll
    for (int s = 0; s < NSTAGES - 1; s++)
        if (s < NITS) load_stage(s, s);

    for (int sit = 0; sit < NITS; sit++) {
        mbar_wait(mbar0 + (sit % NSTAGES) * 8, (sit / NSTAGES) & 1);
        __syncthreads();
        if (sit + NSTAGES - 1 < NITS) load_stage((sit + NSTAGES - 1) % NSTAGES, sit + NSTAGES - 1);

        const uint32_t soff = (sit % NSTAGES) * STAGE_B;
        #pragma unroll
        for (int kb = 0; kb < KPS; kb++) {
            const uint32_t ko = soff + kb * BLK_B;
            #pragma unroll
            for (int ks = 0; ks < 2; ks++) {
                uint32_t af0[4][4], bf[2][4];
                #pragma unroll
                for (int mt = 0; mt < 4; mt++) LDSM4(af0[mt], aAddr[mt][ks] + ko);
                #pragma unroll
                for (int nt2 = 0; nt2 < 2; nt2++) LDSM4(bf[nt2], bAddr[nt2][ks] + ko);
                #pragma unroll
                for (int mt = 0; mt < 4; mt++)
                    #pragma unroll
                    for (int nt = 0; nt < 4; nt++)
                        MMA16816(acc[mt][nt], af0[mt], bf[nt >> 1][(nt & 1) * 2], bf[nt >> 1][(nt & 1) * 2 + 1]);
                if (ATERMS == 2) {
                    uint32_t af1[4][4];
                    #pragma unroll
                    for (int mt = 0; mt < 4; mt++) LDSM4(af1[mt], aAddr[mt][ks] + ko + KPS * BLK_B);
                    #pragma unroll
                    for (int mt = 0; mt < 4; mt++)
                        #pragma unroll
                        for (int nt = 0; nt < 4; nt++)
                            MMA16816(acc[mt][nt], af1[mt], bf[nt >> 1][(nt & 1) * 2], bf[nt >> 1][(nt & 1) * 2 + 1]);
                }
                if (BTERMS == 2) {
                    uint32_t bfl[2][4];
                    #pragma unroll
                    for (int nt2 = 0; nt2 < 2; nt2++) LDSM4(bfl[nt2], bAddr[nt2][ks] + ko + KPS * BLK_B);
                    #pragma unroll
                    for (int mt = 0; mt < 4; mt++)
                        #pragma unroll
                        for (int nt = 0; nt < 4; nt++)
                            MMA16816(acc[mt][nt], af0[mt], bfl[nt >> 1][(nt & 1) * 2], bfl[nt >> 1][(nt & 1) * 2 + 1]);
                }
            }
        }
    }

    // ---- epilogue ----
    const float* biasE = bias + (size_t)e * bStrideE;
    const int cq = (lane & 3) * 2;
    const int r0 = lane >> 2;
    float b2v[4][2];
    #pragma unroll
    for (int nt = 0; nt < 4; nt++) {
        int n = n0 + wn * 32 + nt * 8 + cq;
        b2v[nt][0] = biasE[n];
        b2v[nt][1] = biasE[n + 1];
    }

    if (LG) {
        // gating epilogue: partial logits = relu(v) . gw2  (scales == gw2 [GHID][NE])
        float* sp = (float*)(smem + NSTAGES * STAGE_B + 64);   // [4 wn][128 rows][NE]
        const float* gw2p = scales;
        #pragma unroll
        for (int mt = 0; mt < 4; mt++) {
            #pragma unroll
            for (int h = 0; h < 2; h++) {
                int row = wm * 64 + mt * 16 + r0 + h * 8;   // local row 0..127
                float p[NE];
                #pragma unroll
                for (int e2 = 0; e2 < NE; e2++) p[e2] = 0.0f;
                #pragma unroll
                for (int nt = 0; nt < 4; nt++) {
                    int n = n0 + wn * 32 + nt * 8 + cq;
                    float v0 = acc[mt][nt][h * 2]     + b2v[nt][0];
                    float v1 = acc[mt][nt][h * 2 + 1] + b2v[nt][1];
                    v0 = fmaxf(v0, 0.0f); v1 = fmaxf(v1, 0.0f);
                    const float* ga = gw2p + (size_t)n * NE;
                    #pragma unroll
                    for (int e2 = 0; e2 < NE; e2++)
                        p[e2] += v0 * ga[e2] + v1 * ga[NE + e2];
                }
                #pragma unroll
                for (int e2 = 0; e2 < NE; e2++) {
                    p[e2] += __shfl_xor_sync(0xFFFFFFFFu, p[e2], 1);
                    p[e2] += __shfl_xor_sync(0xFFFFFFFFu, p[e2], 2);
                }
                if ((lane & 3) == 0) {
                    #pragma unroll
                    for (int e2 = 0; e2 < NE; e2++)
                        sp[((wn * 128) + row) * NE + e2] = p[e2];
                }
            }
        }
        __syncthreads();
        for (int idx = tid; idx < 128 * NE; idx += 256) {
            int row = idx >> 3, e2 = idx & 7;
            float s = sp[row * NE + e2] + sp[(128 + row) * NE + e2]
                    + sp[(256 + row) * NE + e2] + sp[(384 + row) * NE + e2];
            outF[(size_t)blockIdx.x * B_TOK * NE + (size_t)(m0 + row) * NE + e2] = s;
        }
        return;
    }

    #pragma unroll
    for (int mt = 0; mt < 4; mt++) {
        #pragma unroll
        for (int h = 0; h < 2; h++) {
            int row = m0 + wm * 64 + mt * 16 + r0 + h * 8;
            if (row >= M) continue;
            size_t erow = (size_t)e * CAP + row;
            float sc = 1.0f;
            int   tok = 0;
            if (flags & FLAG_DEST) {
                sc  = scales[erow];
                tok = dests[erow];
            }
            #pragma unroll
            for (int nt = 0; nt < 4; nt++) {
                int n = n0 + wn * 32 + nt * 8 + cq;
                float v0 = acc[mt][nt][h * 2]     + b2v[nt][0];
                float v1 = acc[mt][nt][h * 2 + 1] + b2v[nt][1];
                if (flags & FLAG_RELU) { v0 = fmaxf(v0, 0.0f); v1 = fmaxf(v1, 0.0f); }
                if (flags & FLAG_SPLIT) {
                    size_t blk = ((erow >> 7) * (size_t)(N >> 5) + (size_t)(n >> 5)) * BLK_EL;
                    *(__half2*)((__half*)outS + blk + sw_off((int)(erow & 127), n & 31)) =
                        __halves2half2(__float2half_rn(v0), __float2half_rn(v1));
                } else if (flags & FLAG_DEST) {
                    REDG_ADD_V2(outF + (size_t)tok * N + n, v0 * sc, v1 * sc);
                } else {
                    float2 o2; o2.x = v0; o2.y = v1;
                    *(float2*)(outF + (size_t)row * N + n) = o2;
                }
            }
        }
    }
}

// ---------------- fused prep: all weight conversions in ONE kernel ----------------
#define TW1  ((HID/32)*(DIN/32)*NE)     // 16384
#define TWP  TW1
#define TW2  ((HID/32)*(HID/32)*NE)     // 32768
#define TW3  ((DOUT/32)*(HID/32)*NE)    // 16384
#define TGW  ((GHID/32)*(DIN/32))       // 1024
#define TWTOT (TW1+TWP+TW2+TW3+TGW)

__device__ __forceinline__ void conv_tile(const float* W, unsigned short* Wt,
                                          int K, int N, size_t termOff,
                                          int e, int n0, int k0,
                                          float t[32][33])
{
    const float* We = W + (size_t)e * K * N;
    #pragma unroll
    for (int j = 0; j < 4; j++) {
        int k = k0 + threadIdx.y + j * 8;
        t[threadIdx.y + j * 8][threadIdx.x] = We[(size_t)k * N + n0 + threadIdx.x];
    }
    __syncthreads();
    const size_t blkBase = (((size_t)e * (N >> 7) + (size_t)(n0 >> 7)) * (K >> 5) + (size_t)(k0 >> 5)) * BLK_EL;
    #pragma unroll
    for (int j = 0; j < 4; j++) {
        int n = n0 + threadIdx.y + j * 8;
        int k = k0 + threadIdx.x;
        float v = t[threadIdx.x][threadIdx.y + j * 8];
        __half hi = __float2half_rn(v);
        size_t off = blkBase + sw_off(n & 127, k & 31);
        ((__half*)Wt)[off] = hi;
        if (termOff) ((__half*)Wt)[termOff + off] = __float2half_rn(v - __half2float(hi));
    }
}

__global__ void prep_w(const float* __restrict__ w1, const float* __restrict__ wp,
                       const float* __restrict__ w2, const float* __restrict__ w3,
                       const float* __restrict__ gw1,
                       unsigned short* __restrict__ w1t, unsigned short* __restrict__ wpt,
                       unsigned short* __restrict__ w2t, unsigned short* __restrict__ w3t,
                       unsigned short* __restrict__ gwt)
{
    __shared__ float t[32][33];
    int b = blockIdx.x;
    if (b < TW1) {
        int e = b / ((HID/32)*(DIN/32)); int r = b % ((HID/32)*(DIN/32));
        conv_tile(w1, w1t, DIN, HID, 0, e, (r % (HID/32)) * 32, (r / (HID/32)) * 32, t);
    } else if ((b -= TW1) < TWP) {
        int e = b / ((HID/32)*(DIN/32)); int r = b % ((HID/32)*(DIN/32));
        conv_tile(wp, wpt, DIN, HID, 0, e, (r % (HID/32)) * 32, (r / (HID/32)) * 32, t);
    } else if ((b -= TWP) < TW2) {
        int e = b / ((HID/32)*(HID/32)); int r = b % ((HID/32)*(HID/32));
        conv_tile(w2, w2t, HID, HID, 0, e, (r % (HID/32)) * 32, (r / (HID/32)) * 32, t);
    } else if ((b -= TW2) < TW3) {
        int e = b / ((DOUT/32)*(HID/32)); int r = b % ((DOUT/32)*(HID/32));
        conv_tile(w3, w3t, HID, DOUT, 0, e, (r % (DOUT/32)) * 32, (r / (DOUT/32)) * 32, t);
    } else {
        b -= TW3;
        conv_tile(gw1, gwt, DIN, GHID, GWT_TERM, 0, (b % (GHID/32)) * 32, (b / (GHID/32)) * 32, t);
    }
}

// ---------------- fused prep: zero_out + convert_x + bias_fuse + counts ----------------
#define ZN4   ((size_t)B_TOK * DOUT / 4)
#define XTOT  ((size_t)B_TOK * DIN)
__global__ __launch_bounds__(256) void prep_small(float4* __restrict__ out,
                                                  const float* __restrict__ x,
                                                  unsigned short* __restrict__ xt,
                                                  const float* __restrict__ b2,
                                                  const float* __restrict__ bp,
                                                  float* __restrict__ b23)
{
    size_t idx = (size_t)blockIdx.x * blockDim.x + threadIdx.x;
    if (idx < ZN4) {
        out[idx] = make_float4(0.f, 0.f, 0.f, 0.f);
    }
    if (idx < XTOT) {
        size_t t = idx / DIN;
        int    k = (int)(idx % DIN);
        float v = x[idx];
        __half hi = __float2half_rn(v);
        __half lo = __float2half_rn(v - __half2float(hi));
        size_t blk = ((t >> 7) * (size_t)(DIN >> 5) + (size_t)(k >> 5)) * BLK_EL
                   + sw_off((int)(t & 127), k & 31);
        ((__half*)xt)[blk]           = hi;
        ((__half*)xt)[XT_TERM + blk] = lo;
    }
    if (idx < NE * HID) b23[idx] = b2[idx] + bp[idx];
    if (idx < NE) g_counts[idx] = 0;
}

// ---------------- gather routed x: vectorized, one 16B chunk per thread ----------------
__global__ __launch_bounds__(256) void tile_gather_x(const float* __restrict__ x,
                                                     unsigned short* __restrict__ xg)
{
    const int e  = blockIdx.y;
    const int mt = blockIdx.x;
    const int M  = g_counts[e];
    const int m0 = mt * 128;
    if (m0 >= M) return;
    const int nrows = min(128, M - m0);
    const size_t base = ((size_t)(e * (CAP / 128) + mt) * (DIN / 32)) * BLK_EL;
    const int nchunks = nrows * (DIN / 8);
    for (int idx = threadIdx.x; idx < nchunks; idx += 256) {
        int row = idx >> 7;
        int c8  = idx & 127;
        int k   = c8 * 8;
        int tok = g_tokens[e * CAP + m0 + row];
        const float4* xp = (const float4*)(x + (size_t)tok * DIN + k);
        float4 a = xp[0], b = xp[1];
        __half h[8];
        h[0] = __float2half_rn(a.x); h[1] = __float2half_rn(a.y);
        h[2] = __float2half_rn(a.z); h[3] = __float2half_rn(a.w);
        h[4] = __float2half_rn(b.x); h[5] = __float2half_rn(b.y);
        h[6] = __float2half_rn(b.z); h[7] = __float2half_rn(b.w);
        size_t off = base + (size_t)(k >> 5) * BLK_EL + sw_off(row, k & 31);
        *(uint4*)((__half*)xg + off) = *(uint4*)h;
    }
}

// ---------------- routing: fused reduce + top-2 + softmax + block-aggregated scatter ----------------
__global__ __launch_bounds__(256) void route_kernel(const float* __restrict__ lpart,
                                                    const float* __restrict__ gb2)
{
    __shared__ int scnt[NE];
    __shared__ int sbase_[NE];
    int t = blockIdx.x * blockDim.x + threadIdx.x;

    float v[NE];
    #pragma unroll
    for (int e = 0; e < NE; e++) v[e] = gb2[e];
    #pragma unroll
    for (int bx = 0; bx < GHID / 128; bx++) {
        const float* lp = lpart + (size_t)bx * B_TOK * NE + (size_t)t * NE;
        #pragma unroll
        for (int e = 0; e < NE; e++) v[e] += lp[e];
    }
    int i0 = 0;
    #pragma unroll
    for (int e = 1; e < NE; e++) if (v[e] > v[i0]) i0 = e;
    int i1 = (i0 == 0) ? 1 : 0;
    #pragma unroll
    for (int e = 0; e < NE; e++) if (e != i0 && v[e] > v[i1]) i1 = e;
    float b = __expf(v[i1] - v[i0]);
    float s = 1.0f + b;
    float w0 = 1.0f / s;
    float w1 = b / s;

    if (threadIdx.x < NE) scnt[threadIdx.x] = 0;
    __syncthreads();
    int l0 = atomicAdd(&scnt[i0], 1);
    int l1 = atomicAdd(&scnt[i1], 1);
    __syncthreads();
    if (threadIdx.x < NE) sbase_[threadIdx.x] = atomicAdd(&g_counts[threadIdx.x], scnt[threadIdx.x]);
    __syncthreads();

    int p0 = sbase_[i0] + l0;
    g_tokens[i0 * CAP + p0] = t;
    g_wts[i0 * CAP + p0]    = w0;
    g_dests[i0 * CAP + p0]  = t;

    int p1 = sbase_[i1] + l1;
    g_tokens[i1 * CAP + p1] = t;
    g_wts[i1 * CAP + p1]    = w1;
    g_dests[i1 * CAP + p1]  = t;
}

// ---------------- host ----------------
#define NST_E 3
#define KPS_E 2
#define DSM_E  (NST_E * 2 * KPS_E * BLK_B + 64)             // 98368; 2 CTAs/SM
#define DSM_L3 (2 * 2 * 3 * BLK_B + 64)                     // 98368; 2 CTAs/SM (KPS=3, NST=2)
#define DSM_G  (2 * 4 * BLK_B + 64 + 4 * 128 * NE * 4)      // 81984; 2 CTAs/SM

extern "C" void kernel_launch(void* const* d_in, const int* in_sizes, int n_in,
                              void* d_out, int out_size) {
    const float* x   = (const float*)d_in[0];
    const float* w1  = (const float*)d_in[1];
    const float* b1  = (const float*)d_in[2];
    const float* w2  = (const float*)d_in[3];
    const float* b2  = (const float*)d_in[4];
    const float* w3  = (const float*)d_in[5];
    const float* b3  = (const float*)d_in[6];
    const float* wp  = (const float*)d_in[7];
    const float* bp  = (const float*)d_in[8];
    const float* gw1 = (const float*)d_in[9];
    const float* gb1 = (const float*)d_in[10];
    const float* gw2 = (const float*)d_in[11];
    const float* gb2 = (const float*)d_in[12];
    float* out = (float*)d_out;

    unsigned short *p_xt, *p_gwt, *p_xg, *p_w1t, *p_wpt, *p_w2t, *p_w3t, *p_hst, *p_ost;
    float *p_lpart, *p_b23, *p_wts;
    int *p_counts, *p_tokens, *p_dests;
    cudaGetSymbolAddress((void**)&p_xt,     g_xt);
    cudaGetSymbolAddress((void**)&p_gwt,    g_gwt);
    cudaGetSymbolAddress((void**)&p_xg,     g_xg);
    cudaGetSymbolAddress((void**)&p_w1t,    g_w1t);
    cudaGetSymbolAddress((void**)&p_wpt,    g_wpt);
    cudaGetSymbolAddress((void**)&p_w2t,    g_w2t);
    cudaGetSymbolAddress((void**)&p_w3t,    g_w3t);
    cudaGetSymbolAddress((void**)&p_hst,    g_hst);
    cudaGetSymbolAddress((void**)&p_ost,    g_ost);
    cudaGetSymbolAddress((void**)&p_lpart,  g_lpart);
    cudaGetSymbolAddress((void**)&p_b23,    g_b23);
    cudaGetSymbolAddress((void**)&p_wts,    g_wts);
    cudaGetSymbolAddress((void**)&p_counts, g_counts);
    cudaGetSymbolAddress((void**)&p_tokens, g_tokens);
    cudaGetSymbolAddress((void**)&p_dests,  g_dests);

    cudaFuncSetAttribute((const void*)mma_gemm<1,1,NST_E,KPS_E,0>,
                         cudaFuncAttributeMaxDynamicSharedMemorySize, DSM_E);
    cudaFuncSetAttribute((const void*)mma_gemm<1,1,2,3,0>,
                         cudaFuncAttributeMaxDynamicSharedMemorySize, DSM_L3);
    cudaFuncSetAttribute((const void*)mma_gemm<2,2,2,1,1>,
                         cudaFuncAttributeMaxDynamicSharedMemorySize, DSM_G);

    // prep: zero out + x split/tile + bias fuse + zero counts (1 launch), weights (1 launch)
    {
        size_t n = XTOT;
        prep_small<<<(unsigned)((n + 255) / 256), 256>>>((float4*)out, x, p_xt, b2, bp, p_b23);
    }
    prep_w<<<TWTOT, dim3(32, 8)>>>(w1, wp, w2, w3, gw1, p_w1t, p_wpt, p_w2t, p_w3t, p_gwt);

    // G1: 3-term gating GEMM with fused partial-logit epilogue (relu(x@gw1+gb1)·gw2)
    mma_gemm<2,2,2,1,1><<<dim3(GHID / BN, B_TOK / BM, 1), 256, DSM_G>>>(
        p_xt, XT_TERM, nullptr, B_TOK / 128,
        p_gwt, GWT_TERM, nullptr,
        gb1, 0,
        p_lpart, nullptr, gw2, nullptr, nullptr, B_TOK,
        DIN / 32, DIN / 32, GHID, FLAG_RELU);

    // routing (fused logit reduce + top-2 + softmax + block-aggregated scatter)
    route_kernel<<<B_TOK / 256, 256>>>(p_lpart, gb2);

    // gather routed x into tiled layout (vectorized 16B chunks)
    tile_gather_x<<<dim3(CAP / 128, NE), 256>>>(x, p_xg);

    // L1: h = relu(x_g @ w1 + b1) -> tiled fp16
    mma_gemm<1,1,NST_E,KPS_E,0><<<dim3(HID / BN, CAP / BM, NE), 256, DSM_E>>>(
        p_xg, 0, nullptr, CAP / 128,
        p_w1t, 0, nullptr,
        b1, HID,
        nullptr, p_hst, nullptr, nullptr, p_counts, 0,
        DIN / 32, DIN / 32, HID, FLAG_RELU | FLAG_SPLIT);

    // L3 (L2 fused via K-concat): o = relu([h|x_g] @ [w2;wp] + b2+bp) -> tiled fp16
    // KPS=3/NST=2: 32 sync iterations instead of 48 on the largest layer
    mma_gemm<1,1,2,3,0><<<dim3(HID / BN, CAP / BM, NE), 256, DSM_L3>>>(
        p_hst, 0, p_xg, CAP / 128,
        p_w2t, 0, p_wpt,
        p_b23, HID,
        nullptr, p_ost, nullptr, nullptr, p_counts, 0,
        (HID + DIN) / 32, HID / 32, HID, FLAG_RELU | FLAG_SPLIT);

    // L4: out[tok] += (o @ w3 + b3) * gate_w   (vector red.global, 2 adds per element)
    mma_gemm<1,1,NST_E,KPS_E,0><<<dim3(DOUT / BN, CAP / BM, NE), 256, DSM_E>>>(
        p_ost, 0, nullptr, CAP / 128,
        p_w3t, 0, nullptr,
        b3, DOUT,
        out, nullptr, p_wts, p_dests, p_counts, 0,
        HID / 32, HID / 32, DOUT, FLAG_DEST);
}